// round 14
// baseline (speedup 1.0000x reference)
#include <cuda_runtime.h>
#include <cuda_fp16.h>
#include <cstdint>
#include <math.h>

// Problem constants
#define S_LEN   2048
#define BATCH   2
#define DMODEL  512
#define NHEAD   8
#define DHEAD   64
#define NROWS   (S_LEN*BATCH)        // 4096
#define CHUNK   128
#define NCHUNK  (S_LEN/CHUNK)        // 16
#define NBH     (BATCH*NHEAD)        // 16
#define ATT_SCALE 0.125f
#define ATT_EPS   1e-5f
#define LN_EPS    1e-5f

// ---------------------------------------------------------------------------
// PTX helpers — arch-agnostic (plain sm_103 target: no tcgen05)
// ---------------------------------------------------------------------------
__device__ __forceinline__ uint32_t smem_u32(const void* p) {
    uint32_t a;
    asm("{ .reg .u64 t; cvta.to.shared.u64 t, %1; cvt.u32.u64 %0, t; }"
        : "=r"(a) : "l"(p));
    return a;
}

#define LDSM4(r, addr) \
    asm volatile("ldmatrix.sync.aligned.m8n8.x4.shared.b16 {%0,%1,%2,%3}, [%4];" \
        : "=r"((r)[0]), "=r"((r)[1]), "=r"((r)[2]), "=r"((r)[3]) : "r"(addr))

#define LDSM4T(r, addr) \
    asm volatile("ldmatrix.sync.aligned.m8n8.x4.trans.shared.b16 {%0,%1,%2,%3}, [%4];" \
        : "=r"((r)[0]), "=r"((r)[1]), "=r"((r)[2]), "=r"((r)[3]) : "r"(addr))

#define MMA_F16(d, a, b) \
    asm volatile("mma.sync.aligned.m16n8k16.row.col.f32.f16.f16.f32 " \
        "{%0,%1,%2,%3}, {%4,%5,%6,%7}, {%8,%9}, {%0,%1,%2,%3};" \
        : "+f"((d)[0]), "+f"((d)[1]), "+f"((d)[2]), "+f"((d)[3]) \
        : "r"((a)[0]), "r"((a)[1]), "r"((a)[2]), "r"((a)[3]), \
          "r"((b)[0]), "r"((b)[1]))

#define CP_ASYNC16(sdst, gsrc) \
    asm volatile("cp.async.cg.shared.global [%0], [%1], 16;" \
        :: "r"(sdst), "l"(gsrc) : "memory")
#define CP_COMMIT() asm volatile("cp.async.commit_group;" ::: "memory")
#define CP_WAIT2()  asm volatile("cp.async.wait_group 2;" ::: "memory")
#define CP_WAIT0()  asm volatile("cp.async.wait_group 0;" ::: "memory")

// ---------------------------------------------------------------------------
// Scratch (static device globals — no allocation allowed)
// ---------------------------------------------------------------------------
__device__ __half g_h16 [NROWS*DMODEL];
__device__ __half g_Wq16 [512*512];
__device__ __half g_Wkv16[512*1024];
__device__ __half g_Wo16 [512*512];

__device__ __half g_Q[NROWS*DMODEL];
__device__ __half g_K[NROWS*DMODEL];
__device__ __half g_V[NROWS*DMODEL];

__device__ __half g_ckv[NBH*NCHUNK*DHEAD*DHEAD];   // fp16 per-chunk KV sums
__device__ float  g_cks[NBH*NCHUNK*DHEAD];

__device__ __half g_AV[NROWS*DMODEL];
__device__ float  g_AO[NROWS*DMODEL];

__device__ int    g_bar;                           // attn grid barrier

__device__ __forceinline__ float elu1(float x) {
    return x > 0.f ? x + 1.f : expf(x);
}

// ---------------------------------------------------------------------------
// Fused convert: all four fp32 tensors to fp16 in ONE launch.
// Also resets the attn grid barrier.
// ---------------------------------------------------------------------------
__global__ __launch_bounds__(256) void convert_all_kernel(
    const float* __restrict__ h,  const float* __restrict__ Wq,
    const float* __restrict__ Wkv, const float* __restrict__ Wo,
    __half* __restrict__ h16, __half* __restrict__ wq16,
    __half* __restrict__ wkv16, __half* __restrict__ wo16)
{
    const int bid = blockIdx.x;
    if (bid == 0 && threadIdx.x == 0) g_bar = 0;
    const float4* src; __half* dst; int i;
    if (bid < 1024)      { src = (const float4*)h;   dst = h16;   i = bid*256 + threadIdx.x; }
    else if (bid < 1152) { src = (const float4*)Wq;  dst = wq16;  i = (bid-1024)*256 + threadIdx.x; }
    else if (bid < 1408) { src = (const float4*)Wkv; dst = wkv16; i = (bid-1152)*256 + threadIdx.x; }
    else                 { src = (const float4*)Wo;  dst = wo16;  i = (bid-1408)*256 + threadIdx.x; }
    float4 a = src[2*i];
    float4 b = src[2*i + 1];
    __half2 p0; p0.x = __float2half_rn(a.x); p0.y = __float2half_rn(a.y);
    __half2 p1; p1.x = __float2half_rn(a.z); p1.y = __float2half_rn(a.w);
    __half2 p2; p2.x = __float2half_rn(b.x); p2.y = __float2half_rn(b.y);
    __half2 p3; p3.x = __float2half_rn(b.z); p3.y = __float2half_rn(b.w);
    uint4 o;
    o.x = *(uint32_t*)&p0; o.y = *(uint32_t*)&p1;
    o.z = *(uint32_t*)&p2; o.w = *(uint32_t*)&p3;
    ((uint4*)dst)[i] = o;
}

// ---------------------------------------------------------------------------
// QKV GEMM tiles: BM=64, BN=128, BK=32, 8 warps, warp tile 32x32, 3 stages.
// ---------------------------------------------------------------------------
#define G_TILEA  (64*80)
#define G_TILEB  (32*272)
#define G_BUFB   (G_TILEA + G_TILEB)
#define GEMM_SMEM (3*G_BUFB)

__global__ __launch_bounds__(256, 3) void qkv_gemm(
    const __half* __restrict__ A, const __half* __restrict__ Bq,
    const __half* __restrict__ Bkv,
    __half* __restrict__ Qo, __half* __restrict__ Ko, __half* __restrict__ Vo)
{
    extern __shared__ char smem[];
    constexpr int K = 512, NT = 16;

    const int bx = blockIdx.x;
    const bool isQ = bx < 4;
    const __half* B = isQ ? Bq : Bkv;
    const int N  = isQ ? 512 : 1024;
    const int n0 = (isQ ? bx : bx - 4)*128;

    const int tid = threadIdx.x;
    const int wid = tid >> 5, lane = tid & 31;
    const int m0 = blockIdx.y*64;
    const int warp_m = wid >> 2, warp_n = wid & 3;
    const uint32_t smb = smem_u32(smem);

    auto issue_chunk = [&](int kt, int buf) {
        const uint32_t sbase = smb + (uint32_t)buf*G_BUFB;
        {
            const int ar = tid >> 2, ac = tid & 3;
            const size_t ga = (size_t)(m0 + ar)*K + (size_t)kt*32 + ac*8;
            CP_ASYNC16(sbase + (uint32_t)(ar*80 + ac*16), A + ga);
        }
        #pragma unroll
        for (int half_ = 0; half_ < 2; ++half_) {
            const int idx = tid + half_*256;
            const int br = idx >> 4, bc = idx & 15;
            const size_t gb = (size_t)(kt*32 + br)*N + n0 + bc*8;
            CP_ASYNC16(sbase + G_TILEA + (uint32_t)(br*272 + bc*16), B + gb);
        }
        CP_COMMIT();
    };

    float d[2][4][4];
    #pragma unroll
    for (int mt = 0; mt < 2; ++mt)
        #pragma unroll
        for (int nt = 0; nt < 4; ++nt)
            #pragma unroll
            for (int e = 0; e < 4; ++e) d[mt][nt][e] = 0.f;

    issue_chunk(0, 0);
    issue_chunk(1, 1);
    issue_chunk(2, 2);

    for (int kt = 0; kt < NT; ++kt) {
        CP_WAIT2();
        __syncthreads();
        const int buf = kt % 3;
        const uint32_t sA = smb + (uint32_t)buf*G_BUFB;
        const uint32_t sB = sA + G_TILEA;

        #pragma unroll
        for (int k16 = 0; k16 < 2; ++k16) {
            uint32_t a[2][4];
            #pragma unroll
            for (int mt = 0; mt < 2; ++mt) {
                const uint32_t r = warp_m*32 + mt*16 + (lane & 15);
                LDSM4(a[mt], sA + r*80 + k16*32 + (lane >> 4)*16);
            }
            uint32_t bfr[4][2];
            #pragma unroll
            for (int p = 0; p < 2; ++p) {
                const uint32_t addr = sB + (k16*16 + (lane & 15))*272
                                    + (warp_n*32 + p*16 + (lane >> 4)*8)*2;
                uint32_t t[4];
                LDSM4T(t, addr);
                bfr[2*p][0] = t[0]; bfr[2*p][1] = t[1];
                bfr[2*p+1][0] = t[2]; bfr[2*p+1][1] = t[3];
            }
            #pragma unroll
            for (int mt = 0; mt < 2; ++mt)
                #pragma unroll
                for (int nt = 0; nt < 4; ++nt)
                    MMA_F16(d[mt][nt], a[mt], bfr[nt]);
        }
        __syncthreads();
        if (kt + 3 < NT) issue_chunk(kt + 3, buf);
    }

    __half* dst = isQ ? Qo : ((n0 < 512) ? Ko : Vo);
    const int coloff = (!isQ && n0 >= 512) ? 512 : 0;
    const bool do_elu = isQ || (n0 < 512);

    const int mb = m0 + warp_m*32;
    const int qr = lane >> 2, qc = (lane & 3)*2;
    #pragma unroll
    for (int mt = 0; mt < 2; ++mt) {
        const int r0 = mb + mt*16 + qr, r1 = r0 + 8;
        #pragma unroll
        for (int nt = 0; nt < 4; ++nt) {
            const int n = n0 + warp_n*32 + nt*8 + qc;
            float v0 = d[mt][nt][0], v1 = d[mt][nt][1];
            float v2 = d[mt][nt][2], v3 = d[mt][nt][3];
            if (do_elu) { v0 = elu1(v0); v1 = elu1(v1); v2 = elu1(v2); v3 = elu1(v3); }
            __half2 p0; p0.x = __float2half_rn(v0); p0.y = __float2half_rn(v1);
            __half2 p1; p1.x = __float2half_rn(v2); p1.y = __float2half_rn(v3);
            const int col = n - coloff;
            *(__half2*)&dst[(size_t)r0*512 + col] = p0;
            *(__half2*)&dst[(size_t)r1*512 + col] = p1;
        }
    }
}

// ---------------------------------------------------------------------------
// Output-projection GEMM: AO = AV @ Wo. BM=64, BN=64 tiles -> grid (8,64) =
// 512 CTAs, 4 CTA/SM (small regs/smem). Warp tile 32x16, 8 warps (2x4).
// ---------------------------------------------------------------------------
#define W_TILEA  (64*80)      // 5120
#define W_TILEB  (32*144)     // 4608 (64 cols * 2B + 16 pad)
#define W_BUFB   (W_TILEA + W_TILEB)
#define WO_SMEM  (3*W_BUFB)   // 29184

__global__ __launch_bounds__(256, 4) void wo_gemm(
    const __half* __restrict__ A, const __half* __restrict__ B,
    float* __restrict__ C)
{
    extern __shared__ char smem[];
    constexpr int K = 512, N = 512, NT = 16;

    const int tid = threadIdx.x;
    const int wid = tid >> 5, lane = tid & 31;
    const int m0 = blockIdx.y*64, n0 = blockIdx.x*64;
    const int warp_m = wid >> 2, warp_n = wid & 3;
    const uint32_t smb = smem_u32(smem);

    auto issue_chunk = [&](int kt, int buf) {
        const uint32_t sbase = smb + (uint32_t)buf*W_BUFB;
        {   // A: 64x32 fp16 = 256 x 16B
            const int ar = tid >> 2, ac = tid & 3;
            const size_t ga = (size_t)(m0 + ar)*K + (size_t)kt*32 + ac*8;
            CP_ASYNC16(sbase + (uint32_t)(ar*80 + ac*16), A + ga);
        }
        {   // B: 32x64 fp16 = 256 x 16B
            const int br = tid >> 3, bc = tid & 7;
            const size_t gb = (size_t)(kt*32 + br)*N + n0 + bc*8;
            CP_ASYNC16(sbase + W_TILEA + (uint32_t)(br*144 + bc*16), B + gb);
        }
        CP_COMMIT();
    };

    float d[2][2][4];
    #pragma unroll
    for (int mt = 0; mt < 2; ++mt)
        #pragma unroll
        for (int nt = 0; nt < 2; ++nt)
            #pragma unroll
            for (int e = 0; e < 4; ++e) d[mt][nt][e] = 0.f;

    issue_chunk(0, 0);
    issue_chunk(1, 1);
    issue_chunk(2, 2);

    for (int kt = 0; kt < NT; ++kt) {
        CP_WAIT2();
        __syncthreads();
        const int buf = kt % 3;
        const uint32_t sA = smb + (uint32_t)buf*W_BUFB;
        const uint32_t sB = sA + W_TILEA;

        #pragma unroll
        for (int k16 = 0; k16 < 2; ++k16) {
            uint32_t a[2][4];
            #pragma unroll
            for (int mt = 0; mt < 2; ++mt) {
                const uint32_t r = warp_m*32 + mt*16 + (lane & 15);
                LDSM4(a[mt], sA + r*80 + k16*32 + (lane >> 4)*16);
            }
            uint32_t bfr[2][2];
            {
                const uint32_t addr = sB + (k16*16 + (lane & 15))*144
                                    + (warp_n*16 + (lane >> 4)*8)*2;
                uint32_t t[4];
                LDSM4T(t, addr);
                bfr[0][0] = t[0]; bfr[0][1] = t[1];
                bfr[1][0] = t[2]; bfr[1][1] = t[3];
            }
            #pragma unroll
            for (int mt = 0; mt < 2; ++mt)
                #pragma unroll
                for (int nt = 0; nt < 2; ++nt)
                    MMA_F16(d[mt][nt], a[mt], bfr[nt]);
        }
        __syncthreads();
        if (kt + 3 < NT) issue_chunk(kt + 3, buf);
    }

    const int mb = m0 + warp_m*32;
    const int qr = lane >> 2, qc = (lane & 3)*2;
    #pragma unroll
    for (int mt = 0; mt < 2; ++mt) {
        const int r0 = mb + mt*16 + qr, r1 = r0 + 8;
        #pragma unroll
        for (int nt = 0; nt < 2; ++nt) {
            const int n = n0 + warp_n*16 + nt*8 + qc;
            float2 p0; p0.x = d[mt][nt][0]; p0.y = d[mt][nt][1];
            float2 p1; p1.x = d[mt][nt][2]; p1.y = d[mt][nt][3];
            *(float2*)&C[(size_t)r0*N + n] = p0;
            *(float2*)&C[(size_t)r1*N + n] = p1;
        }
    }
}

// ---------------------------------------------------------------------------
// FUSED chunk-KV + chunked linear attention (one kernel, grid barrier).
// ---------------------------------------------------------------------------
#define A_Q    0u
#define A_K    18432u
#define A_V    36864u
#define A_ST   55296u
#define A_SC   64512u
#define A_KP   99328u
#define A_DLOC 99584u
#define ATTN_SMEM_BYTES 100096

__global__ __launch_bounds__(256, 2) void attn_kernel(
    const __half* __restrict__ Q16, const __half* __restrict__ K16,
    const __half* __restrict__ V16, __half* __restrict__ ckv,
    float* __restrict__ cks, __half* __restrict__ AV)
{
    extern __shared__ char sm[];
    const uint32_t smb = smem_u32(sm);

    const int c  = NCHUNK - 1 - blockIdx.x;
    const int bh = blockIdx.y;
    const int b  = bh >> 3, hh = bh & 7;
    const int tid = threadIdx.x;
    const int wid = tid >> 5, lane = tid & 31;
    const int warp_m = wid >> 2, warp_n = wid & 3;
    const int qr = lane >> 2, qc = (lane & 3)*2;

    #pragma unroll
    for (int t = 0; t < 4; ++t) {
        const int u = tid + t*256;
        const int row = u >> 3, c16 = u & 7;
        const size_t g = (size_t)((c*CHUNK + row)*BATCH + b)*512 + hh*64 + c16*8;
        const uint32_t so = row*144 + c16*16;
        CP_ASYNC16(smb + A_Q + so, Q16 + g);
        CP_ASYNC16(smb + A_K + so, K16 + g);
        CP_ASYNC16(smb + A_V + so, V16 + g);
    }
    CP_COMMIT();
    CP_WAIT0();
    __syncthreads();

    // Phase 1: own chunk's ckv = K^T @ V
    {
        const int wd = wid >> 1, we = wid & 1;
        const int m0c = wd*16, e0c = we*32;

        float acc[4][4];
        #pragma unroll
        for (int nt = 0; nt < 4; ++nt)
            #pragma unroll
            for (int e = 0; e < 4; ++e) acc[nt][e] = 0.f;

        #pragma unroll
        for (int ks = 0; ks < 8; ++ks) {
            uint32_t a[4];
            {
                const uint32_t arow = ks*16 + (lane & 7) + ((lane & 16) >> 1);
                LDSM4T(a, smb + A_K + arow*144 + (m0c + (lane & 8))*2);
            }
            #pragma unroll
            for (int p = 0; p < 2; ++p) {
                uint32_t t[4];
                const uint32_t baddr = smb + A_V + (ks*16 + (lane & 15))*144
                                     + (e0c + p*16 + (lane >> 4)*8)*2;
                LDSM4T(t, baddr);
                uint32_t b0[2] = { t[0], t[1] };
                uint32_t b1[2] = { t[2], t[3] };
                MMA_F16(acc[2*p],     a, b0);
                MMA_F16(acc[2*p + 1], a, b1);
            }
        }

        __half* outp = ckv + (((size_t)bh*NCHUNK + c) << 12);
        #pragma unroll
        for (int nt = 0; nt < 4; ++nt) {
            const int e = e0c + nt*8 + qc;
            const int d0 = m0c + qr, d1 = d0 + 8;
            __half2 p0; p0.x = __float2half_rn(acc[nt][0]); p0.y = __float2half_rn(acc[nt][1]);
            __half2 p1; p1.x = __float2half_rn(acc[nt][2]); p1.y = __float2half_rn(acc[nt][3]);
            *(__half2*)&outp[d0*64 + e] = p0;
            *(__half2*)&outp[d1*64 + e] = p1;
        }

        float* part = (float*)(sm + A_SC);
        if (tid < 128) {
            const int dcol = tid & 63, jh = tid >> 6;
            float s = 0.f;
            #pragma unroll 16
            for (int j = jh*64; j < jh*64 + 64; ++j)
                s += __half2float(*(const __half*)(sm + A_K + j*144 + dcol*2));
            part[tid] = s;
        }
        __syncthreads();
        if (tid < 64)
            cks[(bh*NCHUNK + c)*64 + tid] = part[tid] + part[tid + 64];
    }

    // grid barrier
    __syncthreads();
    if (tid == 0) {
        __threadfence();
        atomicAdd(&g_bar, 1);
        while (atomicAdd(&g_bar, 0) < NCHUNK*NBH) { }
        __threadfence();
    }
    __syncthreads();

    // Phase 2: inline chunk prefix
    {
        float acc[16];
        #pragma unroll
        for (int r = 0; r < 16; ++r) acc[r] = 0.f;
        const uint4* cbase = (const uint4*)(ckv + (((size_t)bh*NCHUNK) << 12));
        for (int cc = 0; cc < c; ++cc) {
            const uint4 v0 = cbase[(cc << 9) + tid*2];
            const uint4 v1 = cbase[(cc << 9) + tid*2 + 1];
            const uint32_t w[8] = { v0.x, v0.y, v0.z, v0.w, v1.x, v1.y, v1.z, v1.w };
            #pragma unroll
            for (int q = 0; q < 8; ++q) {
                const float2 f = __half22float2(*(const __half2*)&w[q]);
                acc[2*q]   += f.x;
                acc[2*q+1] += f.y;
            }
        }
        uint32_t ow[8];
        #pragma unroll
        for (int q = 0; q < 8; ++q) {
            __half2 hp;
            hp.x = __float2half_rn(acc[2*q]);
            hp.y = __float2half_rn(acc[2*q+1]);
            ow[q] = *(uint32_t*)&hp;
        }
        uint4 o0, o1;
        o0.x = ow[0]; o0.y = ow[1]; o0.z = ow[2]; o0.w = ow[3];
        o1.x = ow[4]; o1.y = ow[5]; o1.z = ow[6]; o1.w = ow[7];
        const int dd = tid >> 2, e0 = (tid & 3)*16;
        *(uint4*)(sm + A_ST + dd*144 + e0*2)      = o0;
        *(uint4*)(sm + A_ST + dd*144 + e0*2 + 16) = o1;

        if (tid < 64) {
            float s = 0.f;
            for (int cc = 0; cc < c; ++cc)
                s += cks[(bh*NCHUNK + cc)*64 + tid];
            ((float*)(sm + A_KP))[tid] = s;
        }
    }
    __syncthreads();

    // Stage 1
    {
        float d1[4][4][4];
        #pragma unroll
        for (int mt = 0; mt < 4; ++mt)
            #pragma unroll
            for (int nt = 0; nt < 4; ++nt)
                #pragma unroll
                for (int e = 0; e < 4; ++e) d1[mt][nt][e] = 0.f;

        #pragma unroll
        for (int ks = 0; ks < 4; ++ks) {
            uint32_t a[4][4];
            #pragma unroll
            for (int mt = 0; mt < 4; ++mt) {
                const uint32_t r = warp_m*64 + mt*16 + (lane & 15);
                LDSM4(a[mt], smb + A_Q + r*144 + ks*32 + (lane >> 4)*16);
            }
            uint32_t bf[4][2];
            #pragma unroll
            for (int p = 0; p < 2; ++p) {
                const uint32_t r = warp_n*32 + p*16 + (lane & 7) + ((lane & 16) >> 1);
                uint32_t t[4];
                LDSM4(t, smb + A_K + r*144 + ks*32 + (lane & 8)*2);
                bf[2*p][0]=t[0]; bf[2*p][1]=t[1]; bf[2*p+1][0]=t[2]; bf[2*p+1][1]=t[3];
            }
            #pragma unroll
            for (int mt = 0; mt < 4; ++mt)
                #pragma unroll
                for (int nt = 0; nt < 4; ++nt)
                    MMA_F16(d1[mt][nt], a[mt], bf[nt]);
        }
        #pragma unroll
        for (int mt = 0; mt < 4; ++mt) {
            const int i0 = warp_m*64 + mt*16 + qr, i1 = i0 + 8;
            #pragma unroll
            for (int nt = 0; nt < 4; ++nt) {
                const int j = warp_n*32 + nt*8 + qc;
                float v0 = (j   <= i0) ? d1[mt][nt][0] : 0.f;
                float v1 = (j+1 <= i0) ? d1[mt][nt][1] : 0.f;
                float v2 = (j   <= i1) ? d1[mt][nt][2] : 0.f;
                float v3 = (j+1 <= i1) ? d1[mt][nt][3] : 0.f;
                __half2 p0; p0.x = __float2half_rn(v0); p0.y = __float2half_rn(v1);
                __half2 p1; p1.x = __float2half_rn(v2); p1.y = __float2half_rn(v3);
                *(__half2*)(sm + A_SC + i0*272 + j*2) = p0;
                *(__half2*)(sm + A_SC + i1*272 + j*2) = p1;
            }
        }
    }
    __syncthreads();

    // Stage 2
    {
        const int i = tid >> 1, half_ = tid & 1;
        float s = 0.f;
        const char* rh = sm + A_SC + i*272 + half_*128;
        #pragma unroll
        for (int j2 = 0; j2 < 32; ++j2) {
            __half2 ph = *(const __half2*)(rh + j2*4);
            s += __half2float(ph.x) + __half2float(ph.y);
        }
        const float* kp = (const float*)(sm + A_KP);
        const char* qh = sm + A_Q + i*144 + half_*64;
        #pragma unroll
        for (int k2 = 0; k2 < 16; ++k2) {
            __half2 ph = *(const __half2*)(qh + k2*4);
            const int k = half_*32 + k2*2;
            s = fmaf(__half2float(ph.x), kp[k],   s);
            s = fmaf(__half2float(ph.y), kp[k+1], s);
        }
        s += __shfl_xor_sync(0xffffffffu, s, 1);
        if (half_ == 0)
            ((float*)(sm + A_DLOC))[i] = 1.f / (s*ATT_SCALE + ATT_EPS);
    }
    __syncthreads();

    // Stage 3
    {
        float d3[4][2][4];
        #pragma unroll
        for (int mt = 0; mt < 4; ++mt)
            #pragma unroll
            for (int nt = 0; nt < 2; ++nt)
                #pragma unroll
                for (int e = 0; e < 4; ++e) d3[mt][nt][e] = 0.f;

        #pragma unroll
        for (int ks = 0; ks < 8; ++ks) {
            uint32_t a[4][4];
            #pragma unroll
            for (int mt = 0; mt < 4; ++mt) {
                const uint32_t r = warp_m*64 + mt*16 + (lane & 15);
                LDSM4(a[mt], smb + A_SC + r*272 + ks*32 + (lane >> 4)*16);
            }
            uint32_t bf[2][2];
            {
                const uint32_t addr = smb + A_V + (ks*16 + (lane & 15))*144
                                    + (warp_n*16 + (lane >> 4)*8)*2;
                uint32_t t[4];
                LDSM4T(t, addr);
                bf[0][0]=t[0]; bf[0][1]=t[1]; bf[1][0]=t[2]; bf[1][1]=t[3];
            }
            #pragma unroll
            for (int mt = 0; mt < 4; ++mt)
                #pragma unroll
                for (int nt = 0; nt < 2; ++nt)
                    MMA_F16(d3[mt][nt], a[mt], bf[nt]);
        }
        #pragma unroll
        for (int ks = 0; ks < 4; ++ks) {
            uint32_t a[4][4];
            #pragma unroll
            for (int mt = 0; mt < 4; ++mt) {
                const uint32_t r = warp_m*64 + mt*16 + (lane & 15);
                LDSM4(a[mt], smb + A_Q + r*144 + ks*32 + (lane >> 4)*16);
            }
            uint32_t bf[2][2];
            {
                const uint32_t addr = smb + A_ST + (ks*16 + (lane & 15))*144
                                    + (warp_n*16 + (lane >> 4)*8)*2;
                uint32_t t[4];
                LDSM4T(t, addr);
                bf[0][0]=t[0]; bf[0][1]=t[1]; bf[1][0]=t[2]; bf[1][1]=t[3];
            }
            #pragma unroll
            for (int mt = 0; mt < 4; ++mt)
                #pragma unroll
                for (int nt = 0; nt < 2; ++nt)
                    MMA_F16(d3[mt][nt], a[mt], bf[nt]);
        }

        const float* dloc = (const float*)(sm + A_DLOC);
        __half2* AV2 = (__half2*)AV;
        #pragma unroll
        for (int mt = 0; mt < 4; ++mt) {
            const int i0 = warp_m*64 + mt*16 + qr, i1 = i0 + 8;
            const float sc0 = ATT_SCALE * dloc[i0];
            const float sc1 = ATT_SCALE * dloc[i1];
            const size_t g0 = (size_t)((c*CHUNK + i0)*BATCH + b)*256 + hh*32;
            const size_t g1 = (size_t)((c*CHUNK + i1)*BATCH + b)*256 + hh*32;
            #pragma unroll
            for (int nt = 0; nt < 2; ++nt) {
                const int n = warp_n*16 + nt*8 + qc;
                __half2 p0, p1;
                p0.x = __float2half_rn(d3[mt][nt][0]*sc0);
                p0.y = __float2half_rn(d3[mt][nt][1]*sc0);
                p1.x = __float2half_rn(d3[mt][nt][2]*sc1);
                p1.y = __float2half_rn(d3[mt][nt][3]*sc1);
                AV2[g0 + (n >> 1)] = p0;
                AV2[g1 + (n >> 1)] = p1;
            }
        }
    }
}

// ---------------------------------------------------------------------------
// LayerNorm(h + attn_out). One block per row (512 cols), 128 threads.
// ---------------------------------------------------------------------------
__global__ __launch_bounds__(128) void ln_kernel(
    const float* __restrict__ h, const float* __restrict__ ao,
    const float* __restrict__ gamma, const float* __restrict__ beta,
    float* __restrict__ out)
{
    const int row = blockIdx.x;
    const int tid = threadIdx.x;
    __shared__ float red[4];

    const float* hp = h  + (size_t)row*512;
    const float* ap = ao + (size_t)row*512;
    float x[4];
    #pragma unroll
    for (int r = 0; r < 4; ++r) x[r] = hp[tid + r*128] + ap[tid + r*128];

    float s = (x[0] + x[1]) + (x[2] + x[3]);
    #pragma unroll
    for (int o = 16; o > 0; o >>= 1) s += __shfl_xor_sync(0xffffffffu, s, o);
    if ((tid & 31) == 0) red[tid >> 5] = s;
    __syncthreads();
    const float mu = (red[0] + red[1] + red[2] + red[3]) * (1.f/512.f);
    __syncthreads();

    float v = 0.f;
    #pragma unroll
    for (int r = 0; r < 4; ++r) { const float d = x[r] - mu; v = fmaf(d, d, v); }
    #pragma unroll
    for (int o = 16; o > 0; o >>= 1) v += __shfl_xor_sync(0xffffffffu, v, o);
    if ((tid & 31) == 0) red[tid >> 5] = v;
    __syncthreads();
    const float var  = (red[0] + red[1] + red[2] + red[3]) * (1.f/512.f);
    const float rstd = rsqrtf(var + LN_EPS);

    #pragma unroll
    for (int r = 0; r < 4; ++r) {
        const int col = tid + r*128;
        out[(size_t)row*512 + col] = (x[r] - mu)*rstd*gamma[col] + beta[col];
    }
}

// ---------------------------------------------------------------------------
extern "C" void kernel_launch(void* const* d_in, const int* in_sizes, int n_in,
                              void* d_out, int out_size)
{
    (void)in_sizes; (void)n_in; (void)out_size;
    const float* h     = (const float*)d_in[0];
    const float* Wq    = (const float*)d_in[1];
    const float* Wkv   = (const float*)d_in[2];
    const float* Wo    = (const float*)d_in[3];
    const float* gamma = (const float*)d_in[4];
    const float* beta  = (const float*)d_in[5];
    float* out = (float*)d_out;

    __half *h16, *wq16, *wkv16, *wo16, *Q16, *K16, *V16, *ckv, *AV;
    float *cks, *AO;
    cudaGetSymbolAddress((void**)&h16,   g_h16);
    cudaGetSymbolAddress((void**)&wq16,  g_Wq16);
    cudaGetSymbolAddress((void**)&wkv16, g_Wkv16);
    cudaGetSymbolAddress((void**)&wo16,  g_Wo16);
    cudaGetSymbolAddress((void**)&Q16,   g_Q);
    cudaGetSymbolAddress((void**)&K16,   g_K);
    cudaGetSymbolAddress((void**)&V16,   g_V);
    cudaGetSymbolAddress((void**)&ckv,   g_ckv);
    cudaGetSymbolAddress((void**)&cks,   g_cks);
    cudaGetSymbolAddress((void**)&AV,    g_AV);
    cudaGetSymbolAddress((void**)&AO,    g_AO);

    cudaFuncSetAttribute(qkv_gemm,    cudaFuncAttributeMaxDynamicSharedMemorySize, GEMM_SMEM);
    cudaFuncSetAttribute(wo_gemm,     cudaFuncAttributeMaxDynamicSharedMemorySize, WO_SMEM);
    cudaFuncSetAttribute(attn_kernel, cudaFuncAttributeMaxDynamicSharedMemorySize, ATTN_SMEM_BYTES);

    convert_all_kernel<<<1536, 256>>>(h, Wq, Wkv, Wo, h16, wq16, wkv16, wo16);

    // merged Q + KV projections: BM=64 tiles, 768 CTAs, 3 CTA/SM
    qkv_gemm<<<dim3(12, 64), 256, GEMM_SMEM>>>(h16, wq16, wkv16, Q16, K16, V16);

    // fused chunk-KV + attention (grid barrier inside; 256 CTAs co-resident)
    attn_kernel<<<dim3(NCHUNK, NBH), 256, ATTN_SMEM_BYTES>>>(
        Q16, K16, V16, ckv, cks, AV);

    // output projection: BM=64, BN=64 tiles, 512 CTAs, 4 CTA/SM
    wo_gemm<<<dim3(8, 64), 256, WO_SMEM>>>(AV, wo16, AO);

    ln_kernel<<<NROWS, 128>>>(h, AO, gamma, beta, out);
}

// round 15
// speedup vs baseline: 1.0557x; 1.0557x over previous
#include <cuda_runtime.h>
#include <cuda_fp16.h>
#include <cstdint>
#include <math.h>

// Problem constants
#define S_LEN   2048
#define BATCH   2
#define DMODEL  512
#define NHEAD   8
#define DHEAD   64
#define NROWS   (S_LEN*BATCH)        // 4096
#define CHUNK   128
#define NCHUNK  (S_LEN/CHUNK)        // 16
#define NBH     (BATCH*NHEAD)        // 16
#define ATT_SCALE 0.125f
#define ATT_EPS   1e-5f
#define LN_EPS    1e-5f

// ---------------------------------------------------------------------------
// PTX helpers — arch-agnostic (plain sm_103 target: no tcgen05)
// ---------------------------------------------------------------------------
__device__ __forceinline__ uint32_t smem_u32(const void* p) {
    uint32_t a;
    asm("{ .reg .u64 t; cvta.to.shared.u64 t, %1; cvt.u32.u64 %0, t; }"
        : "=r"(a) : "l"(p));
    return a;
}

#define LDSM4(r, addr) \
    asm volatile("ldmatrix.sync.aligned.m8n8.x4.shared.b16 {%0,%1,%2,%3}, [%4];" \
        : "=r"((r)[0]), "=r"((r)[1]), "=r"((r)[2]), "=r"((r)[3]) : "r"(addr))

#define LDSM4T(r, addr) \
    asm volatile("ldmatrix.sync.aligned.m8n8.x4.trans.shared.b16 {%0,%1,%2,%3}, [%4];" \
        : "=r"((r)[0]), "=r"((r)[1]), "=r"((r)[2]), "=r"((r)[3]) : "r"(addr))

#define MMA_F16(d, a, b) \
    asm volatile("mma.sync.aligned.m16n8k16.row.col.f32.f16.f16.f32 " \
        "{%0,%1,%2,%3}, {%4,%5,%6,%7}, {%8,%9}, {%0,%1,%2,%3};" \
        : "+f"((d)[0]), "+f"((d)[1]), "+f"((d)[2]), "+f"((d)[3]) \
        : "r"((a)[0]), "r"((a)[1]), "r"((a)[2]), "r"((a)[3]), \
          "r"((b)[0]), "r"((b)[1]))

#define CP_ASYNC16(sdst, gsrc) \
    asm volatile("cp.async.cg.shared.global [%0], [%1], 16;" \
        :: "r"(sdst), "l"(gsrc) : "memory")
#define CP_COMMIT() asm volatile("cp.async.commit_group;" ::: "memory")
#define CP_WAIT2()  asm volatile("cp.async.wait_group 2;" ::: "memory")
#define CP_WAIT0()  asm volatile("cp.async.wait_group 0;" ::: "memory")

// ---------------------------------------------------------------------------
// Scratch (static device globals — no allocation allowed)
// ---------------------------------------------------------------------------
__device__ __half g_h16 [NROWS*DMODEL];
__device__ __half g_Wq16 [512*512];
__device__ __half g_Wkv16[512*1024];
__device__ __half g_Wo16 [512*512];

__device__ __half g_Q[NROWS*DMODEL];
__device__ __half g_K[NROWS*DMODEL];
__device__ __half g_V[NROWS*DMODEL];

__device__ __half g_ckv[NBH*NCHUNK*DHEAD*DHEAD];   // fp16 per-chunk KV sums
__device__ float  g_cks[NBH*NCHUNK*DHEAD];

__device__ __half g_AV[NROWS*DMODEL];
__device__ float  g_AO[NROWS*DMODEL];

__device__ int    g_bar;                           // attn grid barrier

__device__ __forceinline__ float elu1(float x) {
    return x > 0.f ? x + 1.f : expf(x);
}

// ---------------------------------------------------------------------------
// Fused convert: all four fp32 tensors to fp16 in ONE launch.
// Also resets the attn grid barrier.
// ---------------------------------------------------------------------------
__global__ __launch_bounds__(256) void convert_all_kernel(
    const float* __restrict__ h,  const float* __restrict__ Wq,
    const float* __restrict__ Wkv, const float* __restrict__ Wo,
    __half* __restrict__ h16, __half* __restrict__ wq16,
    __half* __restrict__ wkv16, __half* __restrict__ wo16)
{
    const int bid = blockIdx.x;
    if (bid == 0 && threadIdx.x == 0) g_bar = 0;
    const float4* src; __half* dst; int i;
    if (bid < 1024)      { src = (const float4*)h;   dst = h16;   i = bid*256 + threadIdx.x; }
    else if (bid < 1152) { src = (const float4*)Wq;  dst = wq16;  i = (bid-1024)*256 + threadIdx.x; }
    else if (bid < 1408) { src = (const float4*)Wkv; dst = wkv16; i = (bid-1152)*256 + threadIdx.x; }
    else                 { src = (const float4*)Wo;  dst = wo16;  i = (bid-1408)*256 + threadIdx.x; }
    float4 a = src[2*i];
    float4 b = src[2*i + 1];
    __half2 p0; p0.x = __float2half_rn(a.x); p0.y = __float2half_rn(a.y);
    __half2 p1; p1.x = __float2half_rn(a.z); p1.y = __float2half_rn(a.w);
    __half2 p2; p2.x = __float2half_rn(b.x); p2.y = __float2half_rn(b.y);
    __half2 p3; p3.x = __float2half_rn(b.z); p3.y = __float2half_rn(b.w);
    uint4 o;
    o.x = *(uint32_t*)&p0; o.y = *(uint32_t*)&p1;
    o.z = *(uint32_t*)&p2; o.w = *(uint32_t*)&p3;
    ((uint4*)dst)[i] = o;
}

// ---------------------------------------------------------------------------
// QKV GEMM: BM=64, BN=128, BK=32, 8 warps, warp tile 32x32,
// 4-stage cp.async pipeline, ONE sync per iteration, 3 CTA/SM.
// ---------------------------------------------------------------------------
#define G_TILEA  (64*80)
#define G_TILEB  (32*272)
#define G_BUFB   (G_TILEA + G_TILEB)
#define GEMM_SMEM (4*G_BUFB)   // 55296

__global__ __launch_bounds__(256, 3) void qkv_gemm(
    const __half* __restrict__ A, const __half* __restrict__ Bq,
    const __half* __restrict__ Bkv,
    __half* __restrict__ Qo, __half* __restrict__ Ko, __half* __restrict__ Vo)
{
    extern __shared__ char smem[];
    constexpr int K = 512, NT = 16;

    const int bx = blockIdx.x;
    const bool isQ = bx < 4;
    const __half* B = isQ ? Bq : Bkv;
    const int N  = isQ ? 512 : 1024;
    const int n0 = (isQ ? bx : bx - 4)*128;

    const int tid = threadIdx.x;
    const int wid = tid >> 5, lane = tid & 31;
    const int m0 = blockIdx.y*64;
    const int warp_m = wid >> 2, warp_n = wid & 3;
    const uint32_t smb = smem_u32(smem);

    auto issue_chunk = [&](int kt, int buf) {
        const uint32_t sbase = smb + (uint32_t)buf*G_BUFB;
        {
            const int ar = tid >> 2, ac = tid & 3;
            const size_t ga = (size_t)(m0 + ar)*K + (size_t)kt*32 + ac*8;
            CP_ASYNC16(sbase + (uint32_t)(ar*80 + ac*16), A + ga);
        }
        #pragma unroll
        for (int half_ = 0; half_ < 2; ++half_) {
            const int idx = tid + half_*256;
            const int br = idx >> 4, bc = idx & 15;
            const size_t gb = (size_t)(kt*32 + br)*N + n0 + bc*8;
            CP_ASYNC16(sbase + G_TILEA + (uint32_t)(br*272 + bc*16), B + gb);
        }
        CP_COMMIT();
    };

    float d[2][4][4];
    #pragma unroll
    for (int mt = 0; mt < 2; ++mt)
        #pragma unroll
        for (int nt = 0; nt < 4; ++nt)
            #pragma unroll
            for (int e = 0; e < 4; ++e) d[mt][nt][e] = 0.f;

    issue_chunk(0, 0);
    issue_chunk(1, 1);
    issue_chunk(2, 2);

    for (int kt = 0; kt < NT; ++kt) {
        CP_WAIT2();
        __syncthreads();                       // single barrier per iteration
        if (kt + 3 < NT) issue_chunk(kt + 3, (kt + 3) & 3);

        const uint32_t sA = smb + (uint32_t)(kt & 3)*G_BUFB;
        const uint32_t sB = sA + G_TILEA;

        #pragma unroll
        for (int k16 = 0; k16 < 2; ++k16) {
            uint32_t a[2][4];
            #pragma unroll
            for (int mt = 0; mt < 2; ++mt) {
                const uint32_t r = warp_m*32 + mt*16 + (lane & 15);
                LDSM4(a[mt], sA + r*80 + k16*32 + (lane >> 4)*16);
            }
            uint32_t bfr[4][2];
            #pragma unroll
            for (int p = 0; p < 2; ++p) {
                const uint32_t addr = sB + (k16*16 + (lane & 15))*272
                                    + (warp_n*32 + p*16 + (lane >> 4)*8)*2;
                uint32_t t[4];
                LDSM4T(t, addr);
                bfr[2*p][0] = t[0]; bfr[2*p][1] = t[1];
                bfr[2*p+1][0] = t[2]; bfr[2*p+1][1] = t[3];
            }
            #pragma unroll
            for (int mt = 0; mt < 2; ++mt)
                #pragma unroll
                for (int nt = 0; nt < 4; ++nt)
                    MMA_F16(d[mt][nt], a[mt], bfr[nt]);
        }
    }

    __half* dst = isQ ? Qo : ((n0 < 512) ? Ko : Vo);
    const int coloff = (!isQ && n0 >= 512) ? 512 : 0;
    const bool do_elu = isQ || (n0 < 512);

    const int mb = m0 + warp_m*32;
    const int qr = lane >> 2, qc = (lane & 3)*2;
    #pragma unroll
    for (int mt = 0; mt < 2; ++mt) {
        const int r0 = mb + mt*16 + qr, r1 = r0 + 8;
        #pragma unroll
        for (int nt = 0; nt < 4; ++nt) {
            const int n = n0 + warp_n*32 + nt*8 + qc;
            float v0 = d[mt][nt][0], v1 = d[mt][nt][1];
            float v2 = d[mt][nt][2], v3 = d[mt][nt][3];
            if (do_elu) { v0 = elu1(v0); v1 = elu1(v1); v2 = elu1(v2); v3 = elu1(v3); }
            __half2 p0; p0.x = __float2half_rn(v0); p0.y = __float2half_rn(v1);
            __half2 p1; p1.x = __float2half_rn(v2); p1.y = __float2half_rn(v3);
            const int col = n - coloff;
            *(__half2*)&dst[(size_t)r0*512 + col] = p0;
            *(__half2*)&dst[(size_t)r1*512 + col] = p1;
        }
    }
}

// ---------------------------------------------------------------------------
// Output-projection GEMM: BM=128, BN=128 (round-12 best), 4-stage pipeline,
// ONE sync per iteration, 2 CTA/SM. grid (4, 32).
// ---------------------------------------------------------------------------
#define W_TILEA  (128*80)     // 10240
#define W_TILEB  (32*272)     // 8704
#define W_BUFB   (W_TILEA + W_TILEB)
#define WO_SMEM  (4*W_BUFB)   // 75776

__global__ __launch_bounds__(256, 2) void wo_gemm(
    const __half* __restrict__ A, const __half* __restrict__ B,
    float* __restrict__ C)
{
    extern __shared__ char smem[];
    constexpr int K = 512, N = 512, NT = 16;

    const int tid = threadIdx.x;
    const int wid = tid >> 5, lane = tid & 31;
    const int m0 = blockIdx.y*128, n0 = blockIdx.x*128;
    const int warp_m = wid >> 2, warp_n = wid & 3;
    const uint32_t smb = smem_u32(smem);

    auto issue_chunk = [&](int kt, int buf) {
        const uint32_t sbase = smb + (uint32_t)buf*W_BUFB;
        #pragma unroll
        for (int half_ = 0; half_ < 2; ++half_) {
            const int idx = tid + half_*256;
            const int ar = idx >> 2, ac = idx & 3;
            const size_t ga = (size_t)(m0 + ar)*K + (size_t)kt*32 + ac*8;
            CP_ASYNC16(sbase + (uint32_t)(ar*80 + ac*16), A + ga);
            const int br = idx >> 4, bc = idx & 15;
            const size_t gb = (size_t)(kt*32 + br)*N + n0 + bc*8;
            CP_ASYNC16(sbase + W_TILEA + (uint32_t)(br*272 + bc*16), B + gb);
        }
        CP_COMMIT();
    };

    float d[4][4][4];
    #pragma unroll
    for (int mt = 0; mt < 4; ++mt)
        #pragma unroll
        for (int nt = 0; nt < 4; ++nt)
            #pragma unroll
            for (int e = 0; e < 4; ++e) d[mt][nt][e] = 0.f;

    issue_chunk(0, 0);
    issue_chunk(1, 1);
    issue_chunk(2, 2);

    for (int kt = 0; kt < NT; ++kt) {
        CP_WAIT2();
        __syncthreads();                       // single barrier per iteration
        if (kt + 3 < NT) issue_chunk(kt + 3, (kt + 3) & 3);

        const uint32_t sA = smb + (uint32_t)(kt & 3)*W_BUFB;
        const uint32_t sB = sA + W_TILEA;

        #pragma unroll
        for (int k16 = 0; k16 < 2; ++k16) {
            uint32_t a[4][4];
            #pragma unroll
            for (int mt = 0; mt < 4; ++mt) {
                const uint32_t r = warp_m*64 + mt*16 + (lane & 15);
                LDSM4(a[mt], sA + r*80 + k16*32 + (lane >> 4)*16);
            }
            uint32_t bfr[4][2];
            #pragma unroll
            for (int p = 0; p < 2; ++p) {
                const uint32_t addr = sB + (k16*16 + (lane & 15))*272
                                    + (warp_n*32 + p*16 + (lane >> 4)*8)*2;
                uint32_t t[4];
                LDSM4T(t, addr);
                bfr[2*p][0] = t[0]; bfr[2*p][1] = t[1];
                bfr[2*p+1][0] = t[2]; bfr[2*p+1][1] = t[3];
            }
            #pragma unroll
            for (int mt = 0; mt < 4; ++mt)
                #pragma unroll
                for (int nt = 0; nt < 4; ++nt)
                    MMA_F16(d[mt][nt], a[mt], bfr[nt]);
        }
    }

    const int mb = m0 + warp_m*64;
    const int qr = lane >> 2, qc = (lane & 3)*2;
    #pragma unroll
    for (int mt = 0; mt < 4; ++mt) {
        const int r0 = mb + mt*16 + qr, r1 = r0 + 8;
        #pragma unroll
        for (int nt = 0; nt < 4; ++nt) {
            const int n = n0 + warp_n*32 + nt*8 + qc;
            float2 p0; p0.x = d[mt][nt][0]; p0.y = d[mt][nt][1];
            float2 p1; p1.x = d[mt][nt][2]; p1.y = d[mt][nt][3];
            *(float2*)&C[(size_t)r0*N + n] = p0;
            *(float2*)&C[(size_t)r1*N + n] = p1;
        }
    }
}

// ---------------------------------------------------------------------------
// FUSED chunk-KV + chunked linear attention (one kernel, grid barrier).
// ---------------------------------------------------------------------------
#define A_Q    0u
#define A_K    18432u
#define A_V    36864u
#define A_ST   55296u
#define A_SC   64512u
#define A_KP   99328u
#define A_DLOC 99584u
#define ATTN_SMEM_BYTES 100096

__global__ __launch_bounds__(256, 2) void attn_kernel(
    const __half* __restrict__ Q16, const __half* __restrict__ K16,
    const __half* __restrict__ V16, __half* __restrict__ ckv,
    float* __restrict__ cks, __half* __restrict__ AV)
{
    extern __shared__ char sm[];
    const uint32_t smb = smem_u32(sm);

    const int c  = NCHUNK - 1 - blockIdx.x;
    const int bh = blockIdx.y;
    const int b  = bh >> 3, hh = bh & 7;
    const int tid = threadIdx.x;
    const int wid = tid >> 5, lane = tid & 31;
    const int warp_m = wid >> 2, warp_n = wid & 3;
    const int qr = lane >> 2, qc = (lane & 3)*2;

    #pragma unroll
    for (int t = 0; t < 4; ++t) {
        const int u = tid + t*256;
        const int row = u >> 3, c16 = u & 7;
        const size_t g = (size_t)((c*CHUNK + row)*BATCH + b)*512 + hh*64 + c16*8;
        const uint32_t so = row*144 + c16*16;
        CP_ASYNC16(smb + A_Q + so, Q16 + g);
        CP_ASYNC16(smb + A_K + so, K16 + g);
        CP_ASYNC16(smb + A_V + so, V16 + g);
    }
    CP_COMMIT();
    CP_WAIT0();
    __syncthreads();

    // Phase 1: own chunk's ckv = K^T @ V
    {
        const int wd = wid >> 1, we = wid & 1;
        const int m0c = wd*16, e0c = we*32;

        float acc[4][4];
        #pragma unroll
        for (int nt = 0; nt < 4; ++nt)
            #pragma unroll
            for (int e = 0; e < 4; ++e) acc[nt][e] = 0.f;

        #pragma unroll
        for (int ks = 0; ks < 8; ++ks) {
            uint32_t a[4];
            {
                const uint32_t arow = ks*16 + (lane & 7) + ((lane & 16) >> 1);
                LDSM4T(a, smb + A_K + arow*144 + (m0c + (lane & 8))*2);
            }
            #pragma unroll
            for (int p = 0; p < 2; ++p) {
                uint32_t t[4];
                const uint32_t baddr = smb + A_V + (ks*16 + (lane & 15))*144
                                     + (e0c + p*16 + (lane >> 4)*8)*2;
                LDSM4T(t, baddr);
                uint32_t b0[2] = { t[0], t[1] };
                uint32_t b1[2] = { t[2], t[3] };
                MMA_F16(acc[2*p],     a, b0);
                MMA_F16(acc[2*p + 1], a, b1);
            }
        }

        __half* outp = ckv + (((size_t)bh*NCHUNK + c) << 12);
        #pragma unroll
        for (int nt = 0; nt < 4; ++nt) {
            const int e = e0c + nt*8 + qc;
            const int d0 = m0c + qr, d1 = d0 + 8;
            __half2 p0; p0.x = __float2half_rn(acc[nt][0]); p0.y = __float2half_rn(acc[nt][1]);
            __half2 p1; p1.x = __float2half_rn(acc[nt][2]); p1.y = __float2half_rn(acc[nt][3]);
            *(__half2*)&outp[d0*64 + e] = p0;
            *(__half2*)&outp[d1*64 + e] = p1;
        }

        float* part = (float*)(sm + A_SC);
        if (tid < 128) {
            const int dcol = tid & 63, jh = tid >> 6;
            float s = 0.f;
            #pragma unroll 16
            for (int j = jh*64; j < jh*64 + 64; ++j)
                s += __half2float(*(const __half*)(sm + A_K + j*144 + dcol*2));
            part[tid] = s;
        }
        __syncthreads();
        if (tid < 64)
            cks[(bh*NCHUNK + c)*64 + tid] = part[tid] + part[tid + 64];
    }

    // grid barrier
    __syncthreads();
    if (tid == 0) {
        __threadfence();
        atomicAdd(&g_bar, 1);
        while (atomicAdd(&g_bar, 0) < NCHUNK*NBH) { }
        __threadfence();
    }
    __syncthreads();

    // Phase 2: inline chunk prefix
    {
        float acc[16];
        #pragma unroll
        for (int r = 0; r < 16; ++r) acc[r] = 0.f;
        const uint4* cbase = (const uint4*)(ckv + (((size_t)bh*NCHUNK) << 12));
        for (int cc = 0; cc < c; ++cc) {
            const uint4 v0 = cbase[(cc << 9) + tid*2];
            const uint4 v1 = cbase[(cc << 9) + tid*2 + 1];
            const uint32_t w[8] = { v0.x, v0.y, v0.z, v0.w, v1.x, v1.y, v1.z, v1.w };
            #pragma unroll
            for (int q = 0; q < 8; ++q) {
                const float2 f = __half22float2(*(const __half2*)&w[q]);
                acc[2*q]   += f.x;
                acc[2*q+1] += f.y;
            }
        }
        uint32_t ow[8];
        #pragma unroll
        for (int q = 0; q < 8; ++q) {
            __half2 hp;
            hp.x = __float2half_rn(acc[2*q]);
            hp.y = __float2half_rn(acc[2*q+1]);
            ow[q] = *(uint32_t*)&hp;
        }
        uint4 o0, o1;
        o0.x = ow[0]; o0.y = ow[1]; o0.z = ow[2]; o0.w = ow[3];
        o1.x = ow[4]; o1.y = ow[5]; o1.z = ow[6]; o1.w = ow[7];
        const int dd = tid >> 2, e0 = (tid & 3)*16;
        *(uint4*)(sm + A_ST + dd*144 + e0*2)      = o0;
        *(uint4*)(sm + A_ST + dd*144 + e0*2 + 16) = o1;

        if (tid < 64) {
            float s = 0.f;
            for (int cc = 0; cc < c; ++cc)
                s += cks[(bh*NCHUNK + cc)*64 + tid];
            ((float*)(sm + A_KP))[tid] = s;
        }
    }
    __syncthreads();

    // Stage 1
    {
        float d1[4][4][4];
        #pragma unroll
        for (int mt = 0; mt < 4; ++mt)
            #pragma unroll
            for (int nt = 0; nt < 4; ++nt)
                #pragma unroll
                for (int e = 0; e < 4; ++e) d1[mt][nt][e] = 0.f;

        #pragma unroll
        for (int ks = 0; ks < 4; ++ks) {
            uint32_t a[4][4];
            #pragma unroll
            for (int mt = 0; mt < 4; ++mt) {
                const uint32_t r = warp_m*64 + mt*16 + (lane & 15);
                LDSM4(a[mt], smb + A_Q + r*144 + ks*32 + (lane >> 4)*16);
            }
            uint32_t bf[4][2];
            #pragma unroll
            for (int p = 0; p < 2; ++p) {
                const uint32_t r = warp_n*32 + p*16 + (lane & 7) + ((lane & 16) >> 1);
                uint32_t t[4];
                LDSM4(t, smb + A_K + r*144 + ks*32 + (lane & 8)*2);
                bf[2*p][0]=t[0]; bf[2*p][1]=t[1]; bf[2*p+1][0]=t[2]; bf[2*p+1][1]=t[3];
            }
            #pragma unroll
            for (int mt = 0; mt < 4; ++mt)
                #pragma unroll
                for (int nt = 0; nt < 4; ++nt)
                    MMA_F16(d1[mt][nt], a[mt], bf[nt]);
        }
        #pragma unroll
        for (int mt = 0; mt < 4; ++mt) {
            const int i0 = warp_m*64 + mt*16 + qr, i1 = i0 + 8;
            #pragma unroll
            for (int nt = 0; nt < 4; ++nt) {
                const int j = warp_n*32 + nt*8 + qc;
                float v0 = (j   <= i0) ? d1[mt][nt][0] : 0.f;
                float v1 = (j+1 <= i0) ? d1[mt][nt][1] : 0.f;
                float v2 = (j   <= i1) ? d1[mt][nt][2] : 0.f;
                float v3 = (j+1 <= i1) ? d1[mt][nt][3] : 0.f;
                __half2 p0; p0.x = __float2half_rn(v0); p0.y = __float2half_rn(v1);
                __half2 p1; p1.x = __float2half_rn(v2); p1.y = __float2half_rn(v3);
                *(__half2*)(sm + A_SC + i0*272 + j*2) = p0;
                *(__half2*)(sm + A_SC + i1*272 + j*2) = p1;
            }
        }
    }
    __syncthreads();

    // Stage 2
    {
        const int i = tid >> 1, half_ = tid & 1;
        float s = 0.f;
        const char* rh = sm + A_SC + i*272 + half_*128;
        #pragma unroll
        for (int j2 = 0; j2 < 32; ++j2) {
            __half2 ph = *(const __half2*)(rh + j2*4);
            s += __half2float(ph.x) + __half2float(ph.y);
        }
        const float* kp = (const float*)(sm + A_KP);
        const char* qh = sm + A_Q + i*144 + half_*64;
        #pragma unroll
        for (int k2 = 0; k2 < 16; ++k2) {
            __half2 ph = *(const __half2*)(qh + k2*4);
            const int k = half_*32 + k2*2;
            s = fmaf(__half2float(ph.x), kp[k],   s);
            s = fmaf(__half2float(ph.y), kp[k+1], s);
        }
        s += __shfl_xor_sync(0xffffffffu, s, 1);
        if (half_ == 0)
            ((float*)(sm + A_DLOC))[i] = 1.f / (s*ATT_SCALE + ATT_EPS);
    }
    __syncthreads();

    // Stage 3
    {
        float d3[4][2][4];
        #pragma unroll
        for (int mt = 0; mt < 4; ++mt)
            #pragma unroll
            for (int nt = 0; nt < 2; ++nt)
                #pragma unroll
                for (int e = 0; e < 4; ++e) d3[mt][nt][e] = 0.f;

        #pragma unroll
        for (int ks = 0; ks < 8; ++ks) {
            uint32_t a[4][4];
            #pragma unroll
            for (int mt = 0; mt < 4; ++mt) {
                const uint32_t r = warp_m*64 + mt*16 + (lane & 15);
                LDSM4(a[mt], smb + A_SC + r*272 + ks*32 + (lane >> 4)*16);
            }
            uint32_t bf[2][2];
            {
                const uint32_t addr = smb + A_V + (ks*16 + (lane & 15))*144
                                    + (warp_n*16 + (lane >> 4)*8)*2;
                uint32_t t[4];
                LDSM4T(t, addr);
                bf[0][0]=t[0]; bf[0][1]=t[1]; bf[1][0]=t[2]; bf[1][1]=t[3];
            }
            #pragma unroll
            for (int mt = 0; mt < 4; ++mt)
                #pragma unroll
                for (int nt = 0; nt < 2; ++nt)
                    MMA_F16(d3[mt][nt], a[mt], bf[nt]);
        }
        #pragma unroll
        for (int ks = 0; ks < 4; ++ks) {
            uint32_t a[4][4];
            #pragma unroll
            for (int mt = 0; mt < 4; ++mt) {
                const uint32_t r = warp_m*64 + mt*16 + (lane & 15);
                LDSM4(a[mt], smb + A_Q + r*144 + ks*32 + (lane >> 4)*16);
            }
            uint32_t bf[2][2];
            {
                const uint32_t addr = smb + A_ST + (ks*16 + (lane & 15))*144
                                    + (warp_n*16 + (lane >> 4)*8)*2;
                uint32_t t[4];
                LDSM4T(t, addr);
                bf[0][0]=t[0]; bf[0][1]=t[1]; bf[1][0]=t[2]; bf[1][1]=t[3];
            }
            #pragma unroll
            for (int mt = 0; mt < 4; ++mt)
                #pragma unroll
                for (int nt = 0; nt < 2; ++nt)
                    MMA_F16(d3[mt][nt], a[mt], bf[nt]);
        }

        const float* dloc = (const float*)(sm + A_DLOC);
        __half2* AV2 = (__half2*)AV;
        #pragma unroll
        for (int mt = 0; mt < 4; ++mt) {
            const int i0 = warp_m*64 + mt*16 + qr, i1 = i0 + 8;
            const float sc0 = ATT_SCALE * dloc[i0];
            const float sc1 = ATT_SCALE * dloc[i1];
            const size_t g0 = (size_t)((c*CHUNK + i0)*BATCH + b)*256 + hh*32;
            const size_t g1 = (size_t)((c*CHUNK + i1)*BATCH + b)*256 + hh*32;
            #pragma unroll
            for (int nt = 0; nt < 2; ++nt) {
                const int n = warp_n*16 + nt*8 + qc;
                __half2 p0, p1;
                p0.x = __float2half_rn(d3[mt][nt][0]*sc0);
                p0.y = __float2half_rn(d3[mt][nt][1]*sc0);
                p1.x = __float2half_rn(d3[mt][nt][2]*sc1);
                p1.y = __float2half_rn(d3[mt][nt][3]*sc1);
                AV2[g0 + (n >> 1)] = p0;
                AV2[g1 + (n >> 1)] = p1;
            }
        }
    }
}

// ---------------------------------------------------------------------------
// LayerNorm(h + attn_out). One block per row (512 cols), 128 threads.
// ---------------------------------------------------------------------------
__global__ __launch_bounds__(128) void ln_kernel(
    const float* __restrict__ h, const float* __restrict__ ao,
    const float* __restrict__ gamma, const float* __restrict__ beta,
    float* __restrict__ out)
{
    const int row = blockIdx.x;
    const int tid = threadIdx.x;
    __shared__ float red[4];

    const float* hp = h  + (size_t)row*512;
    const float* ap = ao + (size_t)row*512;
    float x[4];
    #pragma unroll
    for (int r = 0; r < 4; ++r) x[r] = hp[tid + r*128] + ap[tid + r*128];

    float s = (x[0] + x[1]) + (x[2] + x[3]);
    #pragma unroll
    for (int o = 16; o > 0; o >>= 1) s += __shfl_xor_sync(0xffffffffu, s, o);
    if ((tid & 31) == 0) red[tid >> 5] = s;
    __syncthreads();
    const float mu = (red[0] + red[1] + red[2] + red[3]) * (1.f/512.f);
    __syncthreads();

    float v = 0.f;
    #pragma unroll
    for (int r = 0; r < 4; ++r) { const float d = x[r] - mu; v = fmaf(d, d, v); }
    #pragma unroll
    for (int o = 16; o > 0; o >>= 1) v += __shfl_xor_sync(0xffffffffu, v, o);
    if ((tid & 31) == 0) red[tid >> 5] = v;
    __syncthreads();
    const float var  = (red[0] + red[1] + red[2] + red[3]) * (1.f/512.f);
    const float rstd = rsqrtf(var + LN_EPS);

    #pragma unroll
    for (int r = 0; r < 4; ++r) {
        const int col = tid + r*128;
        out[(size_t)row*512 + col] = (x[r] - mu)*rstd*gamma[col] + beta[col];
    }
}

// ---------------------------------------------------------------------------
extern "C" void kernel_launch(void* const* d_in, const int* in_sizes, int n_in,
                              void* d_out, int out_size)
{
    (void)in_sizes; (void)n_in; (void)out_size;
    const float* h     = (const float*)d_in[0];
    const float* Wq    = (const float*)d_in[1];
    const float* Wkv   = (const float*)d_in[2];
    const float* Wo    = (const float*)d_in[3];
    const float* gamma = (const float*)d_in[4];
    const float* beta  = (const float*)d_in[5];
    float* out = (float*)d_out;

    __half *h16, *wq16, *wkv16, *wo16, *Q16, *K16, *V16, *ckv, *AV;
    float *cks, *AO;
    cudaGetSymbolAddress((void**)&h16,   g_h16);
    cudaGetSymbolAddress((void**)&wq16,  g_Wq16);
    cudaGetSymbolAddress((void**)&wkv16, g_Wkv16);
    cudaGetSymbolAddress((void**)&wo16,  g_Wo16);
    cudaGetSymbolAddress((void**)&Q16,   g_Q);
    cudaGetSymbolAddress((void**)&K16,   g_K);
    cudaGetSymbolAddress((void**)&V16,   g_V);
    cudaGetSymbolAddress((void**)&ckv,   g_ckv);
    cudaGetSymbolAddress((void**)&cks,   g_cks);
    cudaGetSymbolAddress((void**)&AV,    g_AV);
    cudaGetSymbolAddress((void**)&AO,    g_AO);

    cudaFuncSetAttribute(qkv_gemm,    cudaFuncAttributeMaxDynamicSharedMemorySize, GEMM_SMEM);
    cudaFuncSetAttribute(wo_gemm,     cudaFuncAttributeMaxDynamicSharedMemorySize, WO_SMEM);
    cudaFuncSetAttribute(attn_kernel, cudaFuncAttributeMaxDynamicSharedMemorySize, ATTN_SMEM_BYTES);

    convert_all_kernel<<<1536, 256>>>(h, Wq, Wkv, Wo, h16, wq16, wkv16, wo16);

    // merged Q + KV projections: BM=64 tiles, 768 CTAs, 3 CTA/SM, 1 sync/iter
    qkv_gemm<<<dim3(12, 64), 256, GEMM_SMEM>>>(h16, wq16, wkv16, Q16, K16, V16);

    // fused chunk-KV + attention (grid barrier inside; 256 CTAs co-resident)
    attn_kernel<<<dim3(NCHUNK, NBH), 256, ATTN_SMEM_BYTES>>>(
        Q16, K16, V16, ckv, cks, AV);

    // output projection: BM=128, BN=128, grid 128, 2 CTA/SM, 1 sync/iter
    wo_gemm<<<dim3(4, 32), 256, WO_SMEM>>>(AV, wo16, AO);

    ln_kernel<<<NROWS, 128>>>(h, AO, gamma, beta, out);
}

// round 16
// speedup vs baseline: 1.0743x; 1.0176x over previous
#include <cuda_runtime.h>
#include <cuda_fp16.h>
#include <cstdint>
#include <math.h>

// Problem constants
#define S_LEN   2048
#define BATCH   2
#define DMODEL  512
#define NHEAD   8
#define DHEAD   64
#define NROWS   (S_LEN*BATCH)        // 4096
#define CHUNK   128
#define NCHUNK  (S_LEN/CHUNK)        // 16
#define NBH     (BATCH*NHEAD)        // 16
#define ATT_SCALE 0.125f
#define ATT_EPS   1e-5f
#define LN_EPS    1e-5f

// ---------------------------------------------------------------------------
// PTX helpers — arch-agnostic (plain sm_103 target: no tcgen05)
// ---------------------------------------------------------------------------
__device__ __forceinline__ uint32_t smem_u32(const void* p) {
    uint32_t a;
    asm("{ .reg .u64 t; cvta.to.shared.u64 t, %1; cvt.u32.u64 %0, t; }"
        : "=r"(a) : "l"(p));
    return a;
}

#define LDSM4(r, addr) \
    asm volatile("ldmatrix.sync.aligned.m8n8.x4.shared.b16 {%0,%1,%2,%3}, [%4];" \
        : "=r"((r)[0]), "=r"((r)[1]), "=r"((r)[2]), "=r"((r)[3]) : "r"(addr))

#define LDSM4T(r, addr) \
    asm volatile("ldmatrix.sync.aligned.m8n8.x4.trans.shared.b16 {%0,%1,%2,%3}, [%4];" \
        : "=r"((r)[0]), "=r"((r)[1]), "=r"((r)[2]), "=r"((r)[3]) : "r"(addr))

#define MMA_F16(d, a, b) \
    asm volatile("mma.sync.aligned.m16n8k16.row.col.f32.f16.f16.f32 " \
        "{%0,%1,%2,%3}, {%4,%5,%6,%7}, {%8,%9}, {%0,%1,%2,%3};" \
        : "+f"((d)[0]), "+f"((d)[1]), "+f"((d)[2]), "+f"((d)[3]) \
        : "r"((a)[0]), "r"((a)[1]), "r"((a)[2]), "r"((a)[3]), \
          "r"((b)[0]), "r"((b)[1]))

#define CP_ASYNC16(sdst, gsrc) \
    asm volatile("cp.async.cg.shared.global [%0], [%1], 16;" \
        :: "r"(sdst), "l"(gsrc) : "memory")
#define CP_COMMIT() asm volatile("cp.async.commit_group;" ::: "memory")
#define CP_WAIT2()  asm volatile("cp.async.wait_group 2;" ::: "memory")
#define CP_WAIT0()  asm volatile("cp.async.wait_group 0;" ::: "memory")

// ---------------------------------------------------------------------------
// Scratch (static device globals — no allocation allowed)
// ---------------------------------------------------------------------------
__device__ __half g_h16 [NROWS*DMODEL];
__device__ __half g_Wq16 [512*512];
__device__ __half g_Wkv16[512*1024];
__device__ __half g_Wo16 [512*512];

__device__ __half g_Q[NROWS*DMODEL];
__device__ __half g_K[NROWS*DMODEL];
__device__ __half g_V[NROWS*DMODEL];

__device__ __half g_ckv[NBH*NCHUNK*DHEAD*DHEAD];   // fp16 per-chunk KV sums
__device__ float  g_cks[NBH*NCHUNK*DHEAD];

__device__ __half g_AV [NROWS*DMODEL];
__device__ float  g_AO0[NROWS*DMODEL];
__device__ float  g_AO1[NROWS*DMODEL];

__device__ int    g_bar;                           // attn grid barrier

__device__ __forceinline__ float elu1(float x) {
    return x > 0.f ? x + 1.f : expf(x);
}

// ---------------------------------------------------------------------------
// Fused convert: all four fp32 tensors to fp16 in ONE launch.
// Also resets the attn grid barrier.
// ---------------------------------------------------------------------------
__global__ __launch_bounds__(256) void convert_all_kernel(
    const float* __restrict__ h,  const float* __restrict__ Wq,
    const float* __restrict__ Wkv, const float* __restrict__ Wo,
    __half* __restrict__ h16, __half* __restrict__ wq16,
    __half* __restrict__ wkv16, __half* __restrict__ wo16)
{
    const int bid = blockIdx.x;
    if (bid == 0 && threadIdx.x == 0) g_bar = 0;
    const float4* src; __half* dst; int i;
    if (bid < 1024)      { src = (const float4*)h;   dst = h16;   i = bid*256 + threadIdx.x; }
    else if (bid < 1152) { src = (const float4*)Wq;  dst = wq16;  i = (bid-1024)*256 + threadIdx.x; }
    else if (bid < 1408) { src = (const float4*)Wkv; dst = wkv16; i = (bid-1152)*256 + threadIdx.x; }
    else                 { src = (const float4*)Wo;  dst = wo16;  i = (bid-1408)*256 + threadIdx.x; }
    float4 a = src[2*i];
    float4 b = src[2*i + 1];
    __half2 p0; p0.x = __float2half_rn(a.x); p0.y = __float2half_rn(a.y);
    __half2 p1; p1.x = __float2half_rn(a.z); p1.y = __float2half_rn(a.w);
    __half2 p2; p2.x = __float2half_rn(b.x); p2.y = __float2half_rn(b.y);
    __half2 p3; p3.x = __float2half_rn(b.z); p3.y = __float2half_rn(b.w);
    uint4 o;
    o.x = *(uint32_t*)&p0; o.y = *(uint32_t*)&p1;
    o.z = *(uint32_t*)&p2; o.w = *(uint32_t*)&p3;
    ((uint4*)dst)[i] = o;
}

// ---------------------------------------------------------------------------
// QKV GEMM: BM=64, BN=128, BK=32, 8 warps, warp tile 32x32,
// 4-stage cp.async pipeline, ONE sync per iteration, 3 CTA/SM.
// ---------------------------------------------------------------------------
#define G_TILEA  (64*80)
#define G_TILEB  (32*272)
#define G_BUFB   (G_TILEA + G_TILEB)
#define GEMM_SMEM (4*G_BUFB)   // 55296

__global__ __launch_bounds__(256, 3) void qkv_gemm(
    const __half* __restrict__ A, const __half* __restrict__ Bq,
    const __half* __restrict__ Bkv,
    __half* __restrict__ Qo, __half* __restrict__ Ko, __half* __restrict__ Vo)
{
    extern __shared__ char smem[];
    constexpr int K = 512, NT = 16;

    const int bx = blockIdx.x;
    const bool isQ = bx < 4;
    const __half* B = isQ ? Bq : Bkv;
    const int N  = isQ ? 512 : 1024;
    const int n0 = (isQ ? bx : bx - 4)*128;

    const int tid = threadIdx.x;
    const int wid = tid >> 5, lane = tid & 31;
    const int m0 = blockIdx.y*64;
    const int warp_m = wid >> 2, warp_n = wid & 3;
    const uint32_t smb = smem_u32(smem);

    auto issue_chunk = [&](int kt, int buf) {
        const uint32_t sbase = smb + (uint32_t)buf*G_BUFB;
        {
            const int ar = tid >> 2, ac = tid & 3;
            const size_t ga = (size_t)(m0 + ar)*K + (size_t)kt*32 + ac*8;
            CP_ASYNC16(sbase + (uint32_t)(ar*80 + ac*16), A + ga);
        }
        #pragma unroll
        for (int half_ = 0; half_ < 2; ++half_) {
            const int idx = tid + half_*256;
            const int br = idx >> 4, bc = idx & 15;
            const size_t gb = (size_t)(kt*32 + br)*N + n0 + bc*8;
            CP_ASYNC16(sbase + G_TILEA + (uint32_t)(br*272 + bc*16), B + gb);
        }
        CP_COMMIT();
    };

    float d[2][4][4];
    #pragma unroll
    for (int mt = 0; mt < 2; ++mt)
        #pragma unroll
        for (int nt = 0; nt < 4; ++nt)
            #pragma unroll
            for (int e = 0; e < 4; ++e) d[mt][nt][e] = 0.f;

    issue_chunk(0, 0);
    issue_chunk(1, 1);
    issue_chunk(2, 2);

    for (int kt = 0; kt < NT; ++kt) {
        CP_WAIT2();
        __syncthreads();
        if (kt + 3 < NT) issue_chunk(kt + 3, (kt + 3) & 3);

        const uint32_t sA = smb + (uint32_t)(kt & 3)*G_BUFB;
        const uint32_t sB = sA + G_TILEA;

        #pragma unroll
        for (int k16 = 0; k16 < 2; ++k16) {
            uint32_t a[2][4];
            #pragma unroll
            for (int mt = 0; mt < 2; ++mt) {
                const uint32_t r = warp_m*32 + mt*16 + (lane & 15);
                LDSM4(a[mt], sA + r*80 + k16*32 + (lane >> 4)*16);
            }
            uint32_t bfr[4][2];
            #pragma unroll
            for (int p = 0; p < 2; ++p) {
                const uint32_t addr = sB + (k16*16 + (lane & 15))*272
                                    + (warp_n*32 + p*16 + (lane >> 4)*8)*2;
                uint32_t t[4];
                LDSM4T(t, addr);
                bfr[2*p][0] = t[0]; bfr[2*p][1] = t[1];
                bfr[2*p+1][0] = t[2]; bfr[2*p+1][1] = t[3];
            }
            #pragma unroll
            for (int mt = 0; mt < 2; ++mt)
                #pragma unroll
                for (int nt = 0; nt < 4; ++nt)
                    MMA_F16(d[mt][nt], a[mt], bfr[nt]);
        }
    }

    __half* dst = isQ ? Qo : ((n0 < 512) ? Ko : Vo);
    const int coloff = (!isQ && n0 >= 512) ? 512 : 0;
    const bool do_elu = isQ || (n0 < 512);

    const int mb = m0 + warp_m*32;
    const int qr = lane >> 2, qc = (lane & 3)*2;
    #pragma unroll
    for (int mt = 0; mt < 2; ++mt) {
        const int r0 = mb + mt*16 + qr, r1 = r0 + 8;
        #pragma unroll
        for (int nt = 0; nt < 4; ++nt) {
            const int n = n0 + warp_n*32 + nt*8 + qc;
            float v0 = d[mt][nt][0], v1 = d[mt][nt][1];
            float v2 = d[mt][nt][2], v3 = d[mt][nt][3];
            if (do_elu) { v0 = elu1(v0); v1 = elu1(v1); v2 = elu1(v2); v3 = elu1(v3); }
            __half2 p0; p0.x = __float2half_rn(v0); p0.y = __float2half_rn(v1);
            __half2 p1; p1.x = __float2half_rn(v2); p1.y = __float2half_rn(v3);
            const int col = n - coloff;
            *(__half2*)&dst[(size_t)r0*512 + col] = p0;
            *(__half2*)&dst[(size_t)r1*512 + col] = p1;
        }
    }
}

// ---------------------------------------------------------------------------
// Output-projection GEMM, SPLIT-K=2 (plain, no fusion): grid (8, 32) = 256
// CTAs, each BM=128 x BN=128 over K/2 = 256 (8 kt). Partials -> AO0 / AO1.
// 4-stage pipeline, ONE sync per iteration, 2 CTA/SM.
// ---------------------------------------------------------------------------
#define W_TILEA  (128*80)     // 10240
#define W_TILEB  (32*272)     // 8704
#define W_BUFB   (W_TILEA + W_TILEB)
#define WO_SMEM  (4*W_BUFB)   // 75776

__global__ __launch_bounds__(256, 2) void wo_gemm(
    const __half* __restrict__ A, const __half* __restrict__ B,
    float* __restrict__ AO0, float* __restrict__ AO1)
{
    extern __shared__ char smem[];
    constexpr int K = 512, N = 512, NT = 8;

    const int split = blockIdx.x & 1;
    const int n0 = (blockIdx.x >> 1)*128;
    const int m0 = blockIdx.y*128;
    const int kt0 = split*8;
    float* AO = split ? AO1 : AO0;

    const int tid = threadIdx.x;
    const int wid = tid >> 5, lane = tid & 31;
    const int warp_m = wid >> 2, warp_n = wid & 3;
    const uint32_t smb = smem_u32(smem);

    auto issue_chunk = [&](int kt, int buf) {
        const uint32_t sbase = smb + (uint32_t)buf*W_BUFB;
        #pragma unroll
        for (int half_ = 0; half_ < 2; ++half_) {
            const int idx = tid + half_*256;
            const int ar = idx >> 2, ac = idx & 3;
            const size_t ga = (size_t)(m0 + ar)*K + (size_t)(kt0 + kt)*32 + ac*8;
            CP_ASYNC16(sbase + (uint32_t)(ar*80 + ac*16), A + ga);
            const int br = idx >> 4, bc = idx & 15;
            const size_t gb = (size_t)((kt0 + kt)*32 + br)*N + n0 + bc*8;
            CP_ASYNC16(sbase + W_TILEA + (uint32_t)(br*272 + bc*16), B + gb);
        }
        CP_COMMIT();
    };

    float d[4][4][4];
    #pragma unroll
    for (int mt = 0; mt < 4; ++mt)
        #pragma unroll
        for (int nt = 0; nt < 4; ++nt)
            #pragma unroll
            for (int e = 0; e < 4; ++e) d[mt][nt][e] = 0.f;

    issue_chunk(0, 0);
    issue_chunk(1, 1);
    issue_chunk(2, 2);

    for (int kt = 0; kt < NT; ++kt) {
        CP_WAIT2();
        __syncthreads();
        if (kt + 3 < NT) issue_chunk(kt + 3, (kt + 3) & 3);

        const uint32_t sA = smb + (uint32_t)(kt & 3)*W_BUFB;
        const uint32_t sB = sA + W_TILEA;

        #pragma unroll
        for (int k16 = 0; k16 < 2; ++k16) {
            uint32_t a[4][4];
            #pragma unroll
            for (int mt = 0; mt < 4; ++mt) {
                const uint32_t r = warp_m*64 + mt*16 + (lane & 15);
                LDSM4(a[mt], sA + r*80 + k16*32 + (lane >> 4)*16);
            }
            uint32_t bfr[4][2];
            #pragma unroll
            for (int p = 0; p < 2; ++p) {
                const uint32_t addr = sB + (k16*16 + (lane & 15))*272
                                    + (warp_n*32 + p*16 + (lane >> 4)*8)*2;
                uint32_t t[4];
                LDSM4T(t, addr);
                bfr[2*p][0] = t[0]; bfr[2*p][1] = t[1];
                bfr[2*p+1][0] = t[2]; bfr[2*p+1][1] = t[3];
            }
            #pragma unroll
            for (int mt = 0; mt < 4; ++mt)
                #pragma unroll
                for (int nt = 0; nt < 4; ++nt)
                    MMA_F16(d[mt][nt], a[mt], bfr[nt]);
        }
    }

    const int mb = m0 + warp_m*64;
    const int qr = lane >> 2, qc = (lane & 3)*2;
    #pragma unroll
    for (int mt = 0; mt < 4; ++mt) {
        const int r0 = mb + mt*16 + qr, r1 = r0 + 8;
        #pragma unroll
        for (int nt = 0; nt < 4; ++nt) {
            const int n = n0 + warp_n*32 + nt*8 + qc;
            float2 p0; p0.x = d[mt][nt][0]; p0.y = d[mt][nt][1];
            float2 p1; p1.x = d[mt][nt][2]; p1.y = d[mt][nt][3];
            *(float2*)&AO[(size_t)r0*N + n] = p0;
            *(float2*)&AO[(size_t)r1*N + n] = p1;
        }
    }
}

// ---------------------------------------------------------------------------
// FUSED chunk-KV + chunked linear attention (one kernel, grid barrier),
// with causal work-skipping in stages 1 and 3.
// ---------------------------------------------------------------------------
#define A_Q    0u
#define A_K    18432u
#define A_V    36864u
#define A_ST   55296u
#define A_SC   64512u
#define A_KP   99328u
#define A_DLOC 99584u
#define ATTN_SMEM_BYTES 100096

__global__ __launch_bounds__(256, 2) void attn_kernel(
    const __half* __restrict__ Q16, const __half* __restrict__ K16,
    const __half* __restrict__ V16, __half* __restrict__ ckv,
    float* __restrict__ cks, __half* __restrict__ AV)
{
    extern __shared__ char sm[];
    const uint32_t smb = smem_u32(sm);

    const int c  = NCHUNK - 1 - blockIdx.x;
    const int bh = blockIdx.y;
    const int b  = bh >> 3, hh = bh & 7;
    const int tid = threadIdx.x;
    const int wid = tid >> 5, lane = tid & 31;
    const int warp_m = wid >> 2, warp_n = wid & 3;
    const int qr = lane >> 2, qc = (lane & 3)*2;

    #pragma unroll
    for (int t = 0; t < 4; ++t) {
        const int u = tid + t*256;
        const int row = u >> 3, c16 = u & 7;
        const size_t g = (size_t)((c*CHUNK + row)*BATCH + b)*512 + hh*64 + c16*8;
        const uint32_t so = row*144 + c16*16;
        CP_ASYNC16(smb + A_Q + so, Q16 + g);
        CP_ASYNC16(smb + A_K + so, K16 + g);
        CP_ASYNC16(smb + A_V + so, V16 + g);
    }
    CP_COMMIT();
    CP_WAIT0();
    __syncthreads();

    // Phase 1: own chunk's ckv = K^T @ V
    {
        const int wd = wid >> 1, we = wid & 1;
        const int m0c = wd*16, e0c = we*32;

        float acc[4][4];
        #pragma unroll
        for (int nt = 0; nt < 4; ++nt)
            #pragma unroll
            for (int e = 0; e < 4; ++e) acc[nt][e] = 0.f;

        #pragma unroll
        for (int ks = 0; ks < 8; ++ks) {
            uint32_t a[4];
            {
                const uint32_t arow = ks*16 + (lane & 7) + ((lane & 16) >> 1);
                LDSM4T(a, smb + A_K + arow*144 + (m0c + (lane & 8))*2);
            }
            #pragma unroll
            for (int p = 0; p < 2; ++p) {
                uint32_t t[4];
                const uint32_t baddr = smb + A_V + (ks*16 + (lane & 15))*144
                                     + (e0c + p*16 + (lane >> 4)*8)*2;
                LDSM4T(t, baddr);
                uint32_t b0[2] = { t[0], t[1] };
                uint32_t b1[2] = { t[2], t[3] };
                MMA_F16(acc[2*p],     a, b0);
                MMA_F16(acc[2*p + 1], a, b1);
            }
        }

        __half* outp = ckv + (((size_t)bh*NCHUNK + c) << 12);
        #pragma unroll
        for (int nt = 0; nt < 4; ++nt) {
            const int e = e0c + nt*8 + qc;
            const int d0 = m0c + qr, d1 = d0 + 8;
            __half2 p0; p0.x = __float2half_rn(acc[nt][0]); p0.y = __float2half_rn(acc[nt][1]);
            __half2 p1; p1.x = __float2half_rn(acc[nt][2]); p1.y = __float2half_rn(acc[nt][3]);
            *(__half2*)&outp[d0*64 + e] = p0;
            *(__half2*)&outp[d1*64 + e] = p1;
        }

        float* part = (float*)(sm + A_SC);
        if (tid < 128) {
            const int dcol = tid & 63, jh = tid >> 6;
            float s = 0.f;
            #pragma unroll 16
            for (int j = jh*64; j < jh*64 + 64; ++j)
                s += __half2float(*(const __half*)(sm + A_K + j*144 + dcol*2));
            part[tid] = s;
        }
        __syncthreads();
        if (tid < 64)
            cks[(bh*NCHUNK + c)*64 + tid] = part[tid] + part[tid + 64];
    }

    // grid barrier
    __syncthreads();
    if (tid == 0) {
        __threadfence();
        atomicAdd(&g_bar, 1);
        while (atomicAdd(&g_bar, 0) < NCHUNK*NBH) { }
        __threadfence();
    }
    __syncthreads();

    // Phase 2: inline chunk prefix
    {
        float acc[16];
        #pragma unroll
        for (int r = 0; r < 16; ++r) acc[r] = 0.f;
        const uint4* cbase = (const uint4*)(ckv + (((size_t)bh*NCHUNK) << 12));
        for (int cc = 0; cc < c; ++cc) {
            const uint4 v0 = cbase[(cc << 9) + tid*2];
            const uint4 v1 = cbase[(cc << 9) + tid*2 + 1];
            const uint32_t w[8] = { v0.x, v0.y, v0.z, v0.w, v1.x, v1.y, v1.z, v1.w };
            #pragma unroll
            for (int q = 0; q < 8; ++q) {
                const float2 f = __half22float2(*(const __half2*)&w[q]);
                acc[2*q]   += f.x;
                acc[2*q+1] += f.y;
            }
        }
        uint32_t ow[8];
        #pragma unroll
        for (int q = 0; q < 8; ++q) {
            __half2 hp;
            hp.x = __float2half_rn(acc[2*q]);
            hp.y = __float2half_rn(acc[2*q+1]);
            ow[q] = *(uint32_t*)&hp;
        }
        uint4 o0, o1;
        o0.x = ow[0]; o0.y = ow[1]; o0.z = ow[2]; o0.w = ow[3];
        o1.x = ow[4]; o1.y = ow[5]; o1.z = ow[6]; o1.w = ow[7];
        const int dd = tid >> 2, e0 = (tid & 3)*16;
        *(uint4*)(sm + A_ST + dd*144 + e0*2)      = o0;
        *(uint4*)(sm + A_ST + dd*144 + e0*2 + 16) = o1;

        if (tid < 64) {
            float s = 0.f;
            for (int cc = 0; cc < c; ++cc)
                s += cks[(bh*NCHUNK + cc)*64 + tid];
            ((float*)(sm + A_KP))[tid] = s;
        }
    }
    __syncthreads();

    // Stage 1: S = Q @ K^T, masked -> Ssc fp16.
    // Causal skip: warp tiles with warp_m==0 && warp_n>=2 cover j>=64 for
    // rows i<64 — entirely masked. Write zeros, skip all MMAs.
    {
        const bool fully_masked = (warp_m == 0) && (warp_n >= 2);
        if (fully_masked) {
            const __half2 z = __floats2half2_rn(0.f, 0.f);
            #pragma unroll
            for (int mt = 0; mt < 4; ++mt) {
                const int i0 = mt*16 + qr, i1 = i0 + 8;
                #pragma unroll
                for (int nt = 0; nt < 4; ++nt) {
                    const int j = warp_n*32 + nt*8 + qc;
                    *(__half2*)(sm + A_SC + i0*272 + j*2) = z;
                    *(__half2*)(sm + A_SC + i1*272 + j*2) = z;
                }
            }
        } else {
            float d1[4][4][4];
            #pragma unroll
            for (int mt = 0; mt < 4; ++mt)
                #pragma unroll
                for (int nt = 0; nt < 4; ++nt)
                    #pragma unroll
                    for (int e = 0; e < 4; ++e) d1[mt][nt][e] = 0.f;

            #pragma unroll
            for (int ks = 0; ks < 4; ++ks) {
                uint32_t a[4][4];
                #pragma unroll
                for (int mt = 0; mt < 4; ++mt) {
                    const uint32_t r = warp_m*64 + mt*16 + (lane & 15);
                    LDSM4(a[mt], smb + A_Q + r*144 + ks*32 + (lane >> 4)*16);
                }
                uint32_t bf[4][2];
                #pragma unroll
                for (int p = 0; p < 2; ++p) {
                    const uint32_t r = warp_n*32 + p*16 + (lane & 7) + ((lane & 16) >> 1);
                    uint32_t t[4];
                    LDSM4(t, smb + A_K + r*144 + ks*32 + (lane & 8)*2);
                    bf[2*p][0]=t[0]; bf[2*p][1]=t[1]; bf[2*p+1][0]=t[2]; bf[2*p+1][1]=t[3];
                }
                #pragma unroll
                for (int mt = 0; mt < 4; ++mt)
                    #pragma unroll
                    for (int nt = 0; nt < 4; ++nt)
                        MMA_F16(d1[mt][nt], a[mt], bf[nt]);
            }
            #pragma unroll
            for (int mt = 0; mt < 4; ++mt) {
                const int i0 = warp_m*64 + mt*16 + qr, i1 = i0 + 8;
                #pragma unroll
                for (int nt = 0; nt < 4; ++nt) {
                    const int j = warp_n*32 + nt*8 + qc;
                    float v0 = (j   <= i0) ? d1[mt][nt][0] : 0.f;
                    float v1 = (j+1 <= i0) ? d1[mt][nt][1] : 0.f;
                    float v2 = (j   <= i1) ? d1[mt][nt][2] : 0.f;
                    float v3 = (j+1 <= i1) ? d1[mt][nt][3] : 0.f;
                    __half2 p0; p0.x = __float2half_rn(v0); p0.y = __float2half_rn(v1);
                    __half2 p1; p1.x = __float2half_rn(v2); p1.y = __float2half_rn(v3);
                    *(__half2*)(sm + A_SC + i0*272 + j*2) = p0;
                    *(__half2*)(sm + A_SC + i1*272 + j*2) = p1;
                }
            }
        }
    }
    __syncthreads();

    // Stage 2: denominators
    {
        const int i = tid >> 1, half_ = tid & 1;
        float s = 0.f;
        const char* rh = sm + A_SC + i*272 + half_*128;
        #pragma unroll
        for (int j2 = 0; j2 < 32; ++j2) {
            __half2 ph = *(const __half2*)(rh + j2*4);
            s += __half2float(ph.x) + __half2float(ph.y);
        }
        const float* kp = (const float*)(sm + A_KP);
        const char* qh = sm + A_Q + i*144 + half_*64;
        #pragma unroll
        for (int k2 = 0; k2 < 16; ++k2) {
            __half2 ph = *(const __half2*)(qh + k2*4);
            const int k = half_*32 + k2*2;
            s = fmaf(__half2float(ph.x), kp[k],   s);
            s = fmaf(__half2float(ph.y), kp[k+1], s);
        }
        s += __shfl_xor_sync(0xffffffffu, s, 1);
        if (half_ == 0)
            ((float*)(sm + A_DLOC))[i] = 1.f / (s*ATT_SCALE + ATT_EPS);
    }
    __syncthreads();

    // Stage 3: O = Ssc @ V + Q @ St.
    // Causal skip in part A: rows i<64 (warp_m==0) have Ssc[i][j]=0 for
    // j>=64 — ksteps 4..7 contribute nothing.
    {
        float d3[4][2][4];
        #pragma unroll
        for (int mt = 0; mt < 4; ++mt)
            #pragma unroll
            for (int nt = 0; nt < 2; ++nt)
                #pragma unroll
                for (int e = 0; e < 4; ++e) d3[mt][nt][e] = 0.f;

        // part A, ksteps 0..3 (all warps)
        #pragma unroll
        for (int ks = 0; ks < 4; ++ks) {
            uint32_t a[4][4];
            #pragma unroll
            for (int mt = 0; mt < 4; ++mt) {
                const uint32_t r = warp_m*64 + mt*16 + (lane & 15);
                LDSM4(a[mt], smb + A_SC + r*272 + ks*32 + (lane >> 4)*16);
            }
            uint32_t bf[2][2];
            {
                const uint32_t addr = smb + A_V + (ks*16 + (lane & 15))*144
                                    + (warp_n*16 + (lane >> 4)*8)*2;
                uint32_t t[4];
                LDSM4T(t, addr);
                bf[0][0]=t[0]; bf[0][1]=t[1]; bf[1][0]=t[2]; bf[1][1]=t[3];
            }
            #pragma unroll
            for (int mt = 0; mt < 4; ++mt)
                #pragma unroll
                for (int nt = 0; nt < 2; ++nt)
                    MMA_F16(d3[mt][nt], a[mt], bf[nt]);
        }
        // part A, ksteps 4..7 (only rows >= 64 need them)
        if (warp_m == 1) {
            #pragma unroll
            for (int ks = 4; ks < 8; ++ks) {
                uint32_t a[4][4];
                #pragma unroll
                for (int mt = 0; mt < 4; ++mt) {
                    const uint32_t r = 64 + mt*16 + (lane & 15);
                    LDSM4(a[mt], smb + A_SC + r*272 + ks*32 + (lane >> 4)*16);
                }
                uint32_t bf[2][2];
                {
                    const uint32_t addr = smb + A_V + (ks*16 + (lane & 15))*144
                                        + (warp_n*16 + (lane >> 4)*8)*2;
                    uint32_t t[4];
                    LDSM4T(t, addr);
                    bf[0][0]=t[0]; bf[0][1]=t[1]; bf[1][0]=t[2]; bf[1][1]=t[3];
                }
                #pragma unroll
                for (int mt = 0; mt < 4; ++mt)
                    #pragma unroll
                    for (int nt = 0; nt < 2; ++nt)
                        MMA_F16(d3[mt][nt], a[mt], bf[nt]);
            }
        }
        // part B: Q @ St (4 ksteps, all warps)
        #pragma unroll
        for (int ks = 0; ks < 4; ++ks) {
            uint32_t a[4][4];
            #pragma unroll
            for (int mt = 0; mt < 4; ++mt) {
                const uint32_t r = warp_m*64 + mt*16 + (lane & 15);
                LDSM4(a[mt], smb + A_Q + r*144 + ks*32 + (lane >> 4)*16);
            }
            uint32_t bf[2][2];
            {
                const uint32_t addr = smb + A_ST + (ks*16 + (lane & 15))*144
                                    + (warp_n*16 + (lane >> 4)*8)*2;
                uint32_t t[4];
                LDSM4T(t, addr);
                bf[0][0]=t[0]; bf[0][1]=t[1]; bf[1][0]=t[2]; bf[1][1]=t[3];
            }
            #pragma unroll
            for (int mt = 0; mt < 4; ++mt)
                #pragma unroll
                for (int nt = 0; nt < 2; ++nt)
                    MMA_F16(d3[mt][nt], a[mt], bf[nt]);
        }

        const float* dloc = (const float*)(sm + A_DLOC);
        __half2* AV2 = (__half2*)AV;
        #pragma unroll
        for (int mt = 0; mt < 4; ++mt) {
            const int i0 = warp_m*64 + mt*16 + qr, i1 = i0 + 8;
            const float sc0 = ATT_SCALE * dloc[i0];
            const float sc1 = ATT_SCALE * dloc[i1];
            const size_t g0 = (size_t)((c*CHUNK + i0)*BATCH + b)*256 + hh*32;
            const size_t g1 = (size_t)((c*CHUNK + i1)*BATCH + b)*256 + hh*32;
            #pragma unroll
            for (int nt = 0; nt < 2; ++nt) {
                const int n = warp_n*16 + nt*8 + qc;
                __half2 p0, p1;
                p0.x = __float2half_rn(d3[mt][nt][0]*sc0);
                p0.y = __float2half_rn(d3[mt][nt][1]*sc0);
                p1.x = __float2half_rn(d3[mt][nt][2]*sc1);
                p1.y = __float2half_rn(d3[mt][nt][3]*sc1);
                AV2[g0 + (n >> 1)] = p0;
                AV2[g1 + (n >> 1)] = p1;
            }
        }
    }
}

// ---------------------------------------------------------------------------
// LayerNorm(h + AO0 + AO1). One block per row (512 cols), 128 threads.
// ---------------------------------------------------------------------------
__global__ __launch_bounds__(128) void ln_kernel(
    const float* __restrict__ h, const float* __restrict__ ao0,
    const float* __restrict__ ao1,
    const float* __restrict__ gamma, const float* __restrict__ beta,
    float* __restrict__ out)
{
    const int row = blockIdx.x;
    const int tid = threadIdx.x;
    __shared__ float red[4];

    const float* hp = h   + (size_t)row*512;
    const float* a0 = ao0 + (size_t)row*512;
    const float* a1 = ao1 + (size_t)row*512;
    float x[4];
    #pragma unroll
    for (int r = 0; r < 4; ++r)
        x[r] = hp[tid + r*128] + a0[tid + r*128] + a1[tid + r*128];

    float s = (x[0] + x[1]) + (x[2] + x[3]);
    #pragma unroll
    for (int o = 16; o > 0; o >>= 1) s += __shfl_xor_sync(0xffffffffu, s, o);
    if ((tid & 31) == 0) red[tid >> 5] = s;
    __syncthreads();
    const float mu = (red[0] + red[1] + red[2] + red[3]) * (1.f/512.f);
    __syncthreads();

    float v = 0.f;
    #pragma unroll
    for (int r = 0; r < 4; ++r) { const float d = x[r] - mu; v = fmaf(d, d, v); }
    #pragma unroll
    for (int o = 16; o > 0; o >>= 1) v += __shfl_xor_sync(0xffffffffu, v, o);
    if ((tid & 31) == 0) red[tid >> 5] = v;
    __syncthreads();
    const float var  = (red[0] + red[1] + red[2] + red[3]) * (1.f/512.f);
    const float rstd = rsqrtf(var + LN_EPS);

    #pragma unroll
    for (int r = 0; r < 4; ++r) {
        const int col = tid + r*128;
        out[(size_t)row*512 + col] = (x[r] - mu)*rstd*gamma[col] + beta[col];
    }
}

// ---------------------------------------------------------------------------
extern "C" void kernel_launch(void* const* d_in, const int* in_sizes, int n_in,
                              void* d_out, int out_size)
{
    (void)in_sizes; (void)n_in; (void)out_size;
    const float* h     = (const float*)d_in[0];
    const float* Wq    = (const float*)d_in[1];
    const float* Wkv   = (const float*)d_in[2];
    const float* Wo    = (const float*)d_in[3];
    const float* gamma = (const float*)d_in[4];
    const float* beta  = (const float*)d_in[5];
    float* out = (float*)d_out;

    __half *h16, *wq16, *wkv16, *wo16, *Q16, *K16, *V16, *ckv, *AV;
    float *cks, *AO0, *AO1;
    cudaGetSymbolAddress((void**)&h16,   g_h16);
    cudaGetSymbolAddress((void**)&wq16,  g_Wq16);
    cudaGetSymbolAddress((void**)&wkv16, g_Wkv16);
    cudaGetSymbolAddress((void**)&wo16,  g_Wo16);
    cudaGetSymbolAddress((void**)&Q16,   g_Q);
    cudaGetSymbolAddress((void**)&K16,   g_K);
    cudaGetSymbolAddress((void**)&V16,   g_V);
    cudaGetSymbolAddress((void**)&ckv,   g_ckv);
    cudaGetSymbolAddress((void**)&cks,   g_cks);
    cudaGetSymbolAddress((void**)&AV,    g_AV);
    cudaGetSymbolAddress((void**)&AO0,   g_AO0);
    cudaGetSymbolAddress((void**)&AO1,   g_AO1);

    cudaFuncSetAttribute(qkv_gemm,    cudaFuncAttributeMaxDynamicSharedMemorySize, GEMM_SMEM);
    cudaFuncSetAttribute(wo_gemm,     cudaFuncAttributeMaxDynamicSharedMemorySize, WO_SMEM);
    cudaFuncSetAttribute(attn_kernel, cudaFuncAttributeMaxDynamicSharedMemorySize, ATTN_SMEM_BYTES);

    convert_all_kernel<<<1536, 256>>>(h, Wq, Wkv, Wo, h16, wq16, wkv16, wo16);

    // merged Q + KV projections: BM=64 tiles, 768 CTAs, 3 CTA/SM, 1 sync/iter
    qkv_gemm<<<dim3(12, 64), 256, GEMM_SMEM>>>(h16, wq16, wkv16, Q16, K16, V16);

    // fused chunk-KV + attention (grid barrier inside; causal skips)
    attn_kernel<<<dim3(NCHUNK, NBH), 256, ATTN_SMEM_BYTES>>>(
        Q16, K16, V16, ckv, cks, AV);

    // output projection: split-K=2, 256 CTAs, partials to AO0/AO1
    wo_gemm<<<dim3(8, 32), 256, WO_SMEM>>>(AV, wo16, AO0, AO1);

    // out = LayerNorm(h + AO0 + AO1)
    ln_kernel<<<NROWS, 128>>>(h, AO0, AO1, gamma, beta, out);
}